// round 9
// baseline (speedup 1.0000x reference)
#include <cuda_runtime.h>
#include <cstdint>

// y[e, o] = sum_i weight[weight_idx[e], o, i] * values[input_idx[e], i]
// E = 1M, D = 16, N_W = 1024.
//
// R4: contention-free counting sort (1184 blocks for occupancy, packed int2
// payload) + compute with 16 lanes per edge: weight rows in registers,
// x transposed through conflict-free smem, 1-wavefront gathers and stores.

#define D 16
#define NW_MAX 1024
#define PERM_CAP (1 << 21)
#define B_SORT 1184
#define T_SORT 256
#define NSEG 8
#define SEG_B ((B_SORT + NSEG - 1) / NSEG)   // 148

__device__ int  g_bhist [B_SORT * NW_MAX];
__device__ int  g_bstart[B_SORT * NW_MAX];
__device__ int  g_segsum [NSEG * NW_MAX];
__device__ int  g_segbase[NSEG * NW_MAX];
__device__ int  g_tot    [NW_MAX];
__device__ int  g_offsets[NW_MAX];
__device__ int2 g_pe[PERM_CAP];              // {edge id, input_idx}

// ---------------- Pass A: per-block histogram (smem atomics only) -----------

__global__ __launch_bounds__(T_SORT) void passA_hist(
    const int* __restrict__ weight_idx, int E, int chunk)
{
    __shared__ int h[NW_MAX];
    const int b = blockIdx.x;
    for (int i = threadIdx.x; i < NW_MAX; i += T_SORT) h[i] = 0;
    __syncthreads();

    const int lo = b * chunk;
    const int hi = min(lo + chunk, E);
    for (int e = lo + threadIdx.x; e < hi; e += T_SORT)
        atomicAdd(&h[weight_idx[e]], 1);
    __syncthreads();

    for (int i = threadIdx.x; i < NW_MAX; i += T_SORT)
        g_bhist[b * NW_MAX + i] = h[i];
}

// ------------- Pass B1: segmented column scan over blocks (per bin) ---------

__global__ void passB1_colscan(int nblocks)
{
    const int w   = blockIdx.x * blockDim.x + threadIdx.x;
    const int seg = blockIdx.y;
    if (w >= NW_MAX) return;
    const int b0 = seg * SEG_B;
    const int b1 = min(b0 + SEG_B, nblocks);
    int run = 0;
    for (int b = b0; b < b1; b++) {
        const int c = g_bhist[b * NW_MAX + w];   // coalesced across w
        g_bstart[b * NW_MAX + w] = run;
        run += c;
    }
    g_segsum[seg * NW_MAX + w] = run;
}

// ------------- Pass B2: segment combine + exclusive scan of totals ----------

__global__ void passB2_scan()
{
    __shared__ int s[NW_MAX];
    const int w = threadIdx.x;      // 1024 threads
    int base = 0;
#pragma unroll
    for (int g = 0; g < NSEG; g++) {
        g_segbase[g * NW_MAX + w] = base;
        base += g_segsum[g * NW_MAX + w];
    }
    g_tot[w] = base;
    s[w] = base;
    __syncthreads();
#pragma unroll
    for (int off = 1; off < NW_MAX; off <<= 1) {
        const int add = (w >= off) ? s[w - off] : 0;
        __syncthreads();
        s[w] += add;
        __syncthreads();
    }
    g_offsets[w] = s[w] - base;
}

// ---------------- Pass C: scatter via pre-seeded smem cursors ---------------

__global__ __launch_bounds__(T_SORT) void passC_scatter(
    const int* __restrict__ weight_idx,
    const int* __restrict__ input_idx, int E, int chunk)
{
    __shared__ int cur[NW_MAX];
    const int b   = blockIdx.x;
    const int seg = b / SEG_B;
    for (int i = threadIdx.x; i < NW_MAX; i += T_SORT)
        cur[i] = g_offsets[i] + g_segbase[seg * NW_MAX + i] + g_bstart[b * NW_MAX + i];
    __syncthreads();

    const int lo = b * chunk;
    const int hi = min(lo + chunk, E);
    for (int e = lo + threadIdx.x; e < hi; e += T_SORT) {
        const int w  = weight_idx[e];          // coalesced
        const int ii = input_idx[e];           // coalesced
        const int p  = atomicAdd(&cur[w], 1);  // smem only
        g_pe[p] = make_int2(e, ii);            // single 8B scattered store
    }
}

// ------------- Compute: one CTA per weight, 16 lanes per edge ---------------

__global__ __launch_bounds__(256) void compute_sorted_kernel(
    const float* __restrict__ values,   // [N_POOL, 16]
    const float* __restrict__ weight,   // [N_W, 256]
    float* __restrict__ out)            // [E, 16]
{
    __shared__ float sx[8][32][D];      // 16 KB; rows stride 16 -> conflict-free

    const int w      = blockIdx.x;
    const int tid    = threadIdx.x;
    const int lane   = tid & 15;        // output row o
    const int warpId = tid >> 5;
    const int wl     = tid & 31;
    const int half   = wl >> 4;         // group within warp

    // this lane's weight row (loop-invariant, registers)
    const float4* wr4 = reinterpret_cast<const float4*>(weight)
                        + (size_t)w * (D * D / 4) + lane * 4;
    const float4 wa = __ldg(&wr4[0]);
    const float4 wb = __ldg(&wr4[1]);
    const float4 wc = __ldg(&wr4[2]);
    const float4 wd = __ldg(&wr4[3]);

    const int start = g_offsets[w];
    const int count = g_tot[w];

    for (int base = warpId * 32; base < count; base += 8 * 32) {
        const int r = base + wl;
        int2 pe = make_int2(0, 0);
        if (r < count) pe = g_pe[start + r];      // coalesced 8B
        const int nslots = min(32, count - base);

        // phase 1: gather x for up to 32 edges (16 gathers in flight)
#pragma unroll
        for (int k = 0; k < 16; k++) {
            if (2 * k >= nslots) break;           // uniform across warp
            const int  s     = 2 * k + half;
            const bool valid = s < nslots;
            const int  ii    = __shfl_sync(0xFFFFFFFFu, pe.y, valid ? s : 0);
            float xl = 0.0f;
            if (valid) xl = __ldg(&values[(size_t)ii * D + lane]);
            sx[warpId][s][lane] = xl;
        }
        __syncwarp();

        // phase 2: compute y[lane] and scatter-store (1 wf/edge)
#pragma unroll
        for (int k = 0; k < 16; k++) {
            if (2 * k >= nslots) break;           // uniform across warp
            const int  s     = 2 * k + half;
            const bool valid = s < nslots;
            const int  e     = __shfl_sync(0xFFFFFFFFu, pe.x, valid ? s : 0);

            const float4* xs = reinterpret_cast<const float4*>(sx[warpId][s]);
            const float4 x0 = xs[0], x1 = xs[1], x2 = xs[2], x3 = xs[3];

            float acc;
            acc = fmaf(wa.x, x0.x, wa.y * x0.y);
            acc = fmaf(wa.z, x0.z, acc); acc = fmaf(wa.w, x0.w, acc);
            acc = fmaf(wb.x, x1.x, acc); acc = fmaf(wb.y, x1.y, acc);
            acc = fmaf(wb.z, x1.z, acc); acc = fmaf(wb.w, x1.w, acc);
            acc = fmaf(wc.x, x2.x, acc); acc = fmaf(wc.y, x2.y, acc);
            acc = fmaf(wc.z, x2.z, acc); acc = fmaf(wc.w, x2.w, acc);
            acc = fmaf(wd.x, x3.x, acc); acc = fmaf(wd.y, x3.y, acc);
            acc = fmaf(wd.z, x3.z, acc); acc = fmaf(wd.w, x3.w, acc);

            if (valid) out[(size_t)e * D + lane] = acc;
        }
        __syncwarp();
    }
}

// ---------------- fallback (R1 kernel) for unexpected shapes ----------------

__global__ __launch_bounds__(256) void edge_linear_fallback(
    const float* __restrict__ values,
    const float4* __restrict__ weight4,
    const int* __restrict__ input_idx,
    const int* __restrict__ weight_idx,
    float* __restrict__ out, int E)
{
    const int gtid = blockIdx.x * blockDim.x + threadIdx.x;
    const int edge = gtid >> 4;
    const int lane = threadIdx.x & 15;
    if (edge >= E) return;

    const int ii = __ldg(&input_idx[edge]);
    const int wi = __ldg(&weight_idx[edge]);
    const float xl = __ldg(&values[(size_t)ii * D + lane]);

    const float4* wr = weight4 + (size_t)wi * (D * D / 4) + lane * 4;
    const float4 a = __ldg(&wr[0]);
    const float4 b = __ldg(&wr[1]);
    const float4 c = __ldg(&wr[2]);
    const float4 d = __ldg(&wr[3]);
    const float wrow[D] = {a.x, a.y, a.z, a.w,
                           b.x, b.y, b.z, b.w,
                           c.x, c.y, c.z, c.w,
                           d.x, d.y, d.z, d.w};

    float acc = 0.0f;
#pragma unroll
    for (int i = 0; i < D; i++)
        acc = fmaf(wrow[i], __shfl_sync(0xFFFFFFFFu, xl, i, 16), acc);

    out[(size_t)edge * D + lane] = acc;
}

extern "C" void kernel_launch(void* const* d_in, const int* in_sizes, int n_in,
                              void* d_out, int out_size)
{
    const float* values     = (const float*)d_in[0];
    const float* weight     = (const float*)d_in[1];
    const int*   input_idx  = (const int*)d_in[2];
    const int*   weight_idx = (const int*)d_in[3];
    float*       out        = (float*)d_out;

    const int E  = in_sizes[2];
    const int NW = in_sizes[1] / (D * D);

    if (NW != NW_MAX || E > PERM_CAP) {
        const int threads = 256;
        const long long total = (long long)E * 16;
        edge_linear_fallback<<<(int)((total + threads - 1) / threads), threads>>>(
            values, (const float4*)weight, input_idx, weight_idx, out, E);
        return;
    }

    const int chunk = (E + B_SORT - 1) / B_SORT;

    passA_hist    <<<B_SORT, T_SORT>>>(weight_idx, E, chunk);
    passB1_colscan<<<dim3(NW_MAX / 256, NSEG), 256>>>(B_SORT);
    passB2_scan   <<<1, NW_MAX>>>();
    passC_scatter <<<B_SORT, T_SORT>>>(weight_idx, input_idx, E, chunk);
    compute_sorted_kernel<<<NW_MAX, 256>>>(values, weight, out);
}

// round 10
// speedup vs baseline: 1.3259x; 1.3259x over previous
#include <cuda_runtime.h>
#include <cstdint>

// y[e, o] = sum_i weight[weight_idx[e], o, i] * values[input_idx[e], i]
// E = 1M, D = 16, N_W = 1024.
//
// Pipeline:
//   A) per-block smem histogram of weight_idx, recording each edge's rank
//      within (block, bin) as u16  -> no contended atomics anywhere later
//   B) segmented column scan + bin-total exclusive scan
//   C) atomic-free scatter: p = cur[bin] + rank[e]; writes packed {e, input_idx}
//   D) compute: one CTA per weight. Warp-cooperative smem transpose for x
//      gather / y store (1 wavefront per edge each); per-thread straight-line
//      16x16 matvec using packed fma.rn.f32x2 (8 independent acc chains).

#define D 16
#define NW_MAX 1024
#define PERM_CAP (1 << 21)
#define B_SORT 1184
#define T_SORT 256
#define NSEG 8
#define SEG_B ((B_SORT + NSEG - 1) / NSEG)   // 148
#define PAD 20                               // smem row stride (floats): 16B-aligned, conflict-free

__device__ int            g_bhist  [B_SORT * NW_MAX];
__device__ int            g_bstart [B_SORT * NW_MAX];
__device__ int            g_segsum [NSEG * NW_MAX];
__device__ int            g_segbase[NSEG * NW_MAX];
__device__ int            g_tot    [NW_MAX];
__device__ int            g_offsets[NW_MAX];
__device__ unsigned short g_rank[PERM_CAP];
__device__ int2           g_pe  [PERM_CAP];   // {edge id, input_idx}

// ---------------- Pass A: histogram + rank recording ------------------------

__global__ __launch_bounds__(T_SORT) void passA_hist(
    const int* __restrict__ weight_idx, int E, int chunk)
{
    __shared__ int h[NW_MAX];
    const int b = blockIdx.x;
    for (int i = threadIdx.x; i < NW_MAX; i += T_SORT) h[i] = 0;
    __syncthreads();

    const int lo = b * chunk;
    const int hi = min(lo + chunk, E);
    for (int e = lo + threadIdx.x; e < hi; e += T_SORT) {
        const int w = weight_idx[e];
        const int r = atomicAdd(&h[w], 1);       // smem only
        g_rank[e] = (unsigned short)r;           // coalesced 2B store
    }
    __syncthreads();

    for (int i = threadIdx.x; i < NW_MAX; i += T_SORT)
        g_bhist[b * NW_MAX + i] = h[i];
}

// ------------- Pass B1: segmented column scan over blocks (per bin) ---------

__global__ void passB1_colscan(int nblocks)
{
    const int w   = blockIdx.x * blockDim.x + threadIdx.x;
    const int seg = blockIdx.y;
    if (w >= NW_MAX) return;
    const int b0 = seg * SEG_B;
    const int b1 = min(b0 + SEG_B, nblocks);
    int run = 0;
    for (int b = b0; b < b1; b++) {
        const int c = g_bhist[b * NW_MAX + w];   // coalesced across w
        g_bstart[b * NW_MAX + w] = run;
        run += c;
    }
    g_segsum[seg * NW_MAX + w] = run;
}

// ------------- Pass B2: segment combine + exclusive scan of totals ----------

__global__ void passB2_scan()
{
    __shared__ int s[NW_MAX];
    const int w = threadIdx.x;      // 1024 threads
    int base = 0;
#pragma unroll
    for (int g = 0; g < NSEG; g++) {
        g_segbase[g * NW_MAX + w] = base;
        base += g_segsum[g * NW_MAX + w];
    }
    g_tot[w] = base;
    s[w] = base;
    __syncthreads();
#pragma unroll
    for (int off = 1; off < NW_MAX; off <<= 1) {
        const int add = (w >= off) ? s[w - off] : 0;
        __syncthreads();
        s[w] += add;
        __syncthreads();
    }
    g_offsets[w] = s[w] - base;
}

// ---------------- Pass C: atomic-free scatter --------------------------------

__global__ __launch_bounds__(T_SORT) void passC_scatter(
    const int* __restrict__ weight_idx,
    const int* __restrict__ input_idx, int E, int chunk)
{
    __shared__ int cur[NW_MAX];
    const int b   = blockIdx.x;
    const int seg = b / SEG_B;
    for (int i = threadIdx.x; i < NW_MAX; i += T_SORT)
        cur[i] = g_offsets[i] + g_segbase[seg * NW_MAX + i] + g_bstart[b * NW_MAX + i];
    __syncthreads();

    const int lo = b * chunk;
    const int hi = min(lo + chunk, E);
    for (int e = lo + threadIdx.x; e < hi; e += T_SORT) {
        const int w             = weight_idx[e];      // coalesced, independent
        const unsigned short rk = g_rank[e];          // coalesced, independent
        const int ii            = input_idx[e];       // coalesced, independent
        const int p             = cur[w] + (int)rk;   // LDS, no atomics
        g_pe[p] = make_int2(e, ii);                   // single 8B store
    }
}

// ---------------- packed f32x2 FMA helper ------------------------------------

__device__ __forceinline__ void fma_f32x2(unsigned long long& d,
                                          unsigned long long a,
                                          unsigned long long b)
{
    asm("fma.rn.f32x2 %0, %1, %2, %0;" : "+l"(d) : "l"(a), "l"(b));
}

__device__ __forceinline__ unsigned long long bcast2(float x)
{
    unsigned long long r;
    asm("mov.b64 %0, {%1, %1};" : "=l"(r) : "f"(x));
    return r;
}

// ------------- Compute: one CTA per weight, warp-transposed I/O --------------

__global__ __launch_bounds__(256) void compute_sorted_kernel(
    const float* __restrict__ values,   // [N_POOL, 16]
    const float* __restrict__ weight,   // [N_W, 16, 16] row-major
    float* __restrict__ out)            // [E, 16]
{
    __shared__ float sWT[D * D];        // transposed: sWT[i*16 + o] = W[o][i]
    __shared__ float sx[8][32][PAD];    // per-warp x/y rows (reused), 20 KB
    __shared__ int2  sei[8][32];        // per-warp {e, ii} per slot

    const int w      = blockIdx.x;
    const int tid    = threadIdx.x;
    const int warpId = tid >> 5;
    const int wl     = tid & 31;
    const int half   = wl >> 4;
    const int l16    = wl & 15;

    // load + transpose W (256 threads, one element each)
    {
        const int o = tid >> 4;
        const int i = tid & 15;
        sWT[i * D + o] = weight[(size_t)w * (D * D) + tid];   // W[o][i]
    }
    __syncthreads();

    const int start = g_offsets[w];
    const int count = g_tot[w];

    for (int base = warpId * 32; base < count; base += 8 * 32) {
        const int r = base + wl;
        int2 pe = make_int2(0, 0);
        if (r < count) pe = g_pe[start + r];    // coalesced 8B
        sei[warpId][wl] = pe;
        __syncwarp();

        const int nvalid = min(32, count - base);   // warp-uniform, >= 1

        // --- cooperative x gather: 1 wavefront per edge ---
        // instr k serves slots 2k (lanes 0-15) and 2k+1 (lanes 16-31)
#pragma unroll
        for (int k = 0; k < 16; k++) {
            const int s  = 2 * k + half;
            const int ii = (s < nvalid) ? sei[warpId][s].y : 0;
            sx[warpId][s][l16] = __ldg(&values[(size_t)ii * D + l16]);
        }
        __syncwarp();

        // --- per-thread straight-line 16x16 matvec on own slot (wl) ---
        {
            const float4* xr = reinterpret_cast<const float4*>(sx[warpId][wl]);
            const float4 x0 = xr[0], x1 = xr[1], x2 = xr[2], x3 = xr[3];
            const float xi[D] = {x0.x, x0.y, x0.z, x0.w,
                                 x1.x, x1.y, x1.z, x1.w,
                                 x2.x, x2.y, x2.z, x2.w,
                                 x3.x, x3.y, x3.z, x3.w};

            unsigned long long acc[8];
#pragma unroll
            for (int p = 0; p < 8; p++) acc[p] = 0ULL;   // {0.f, 0.f}

#pragma unroll
            for (int i = 0; i < D; i++) {
                const unsigned long long xx = bcast2(xi[i]);
                const ulonglong2* wt =
                    reinterpret_cast<const ulonglong2*>(&sWT[i * D]);
                const ulonglong2 wA = wt[0];   // W[i][0..3]  (broadcast LDS.128)
                const ulonglong2 wB = wt[1];   // W[i][4..7]
                const ulonglong2 wC = wt[2];   // W[i][8..11]
                const ulonglong2 wD = wt[3];   // W[i][12..15]
                fma_f32x2(acc[0], wA.x, xx);
                fma_f32x2(acc[1], wA.y, xx);
                fma_f32x2(acc[2], wB.x, xx);
                fma_f32x2(acc[3], wB.y, xx);
                fma_f32x2(acc[4], wC.x, xx);
                fma_f32x2(acc[5], wC.y, xx);
                fma_f32x2(acc[6], wD.x, xx);
                fma_f32x2(acc[7], wD.y, xx);
            }

            // write y back into own row (conflict-free STS.128)
            ulonglong2* yr = reinterpret_cast<ulonglong2*>(sx[warpId][wl]);
            yr[0] = make_ulonglong2(acc[0], acc[1]);
            yr[1] = make_ulonglong2(acc[2], acc[3]);
            yr[2] = make_ulonglong2(acc[4], acc[5]);
            yr[3] = make_ulonglong2(acc[6], acc[7]);
        }
        __syncwarp();

        // --- cooperative y store: 1 wavefront per edge ---
#pragma unroll
        for (int k = 0; k < 16; k++) {
            const int s = 2 * k + half;
            if (s < nvalid) {
                const int e = sei[warpId][s].x;
                out[(size_t)e * D + l16] = sx[warpId][s][l16];
            }
        }
        __syncwarp();
    }
}

// ---------------- fallback (R1 kernel) for unexpected shapes ----------------

__global__ __launch_bounds__(256) void edge_linear_fallback(
    const float* __restrict__ values,
    const float4* __restrict__ weight4,
    const int* __restrict__ input_idx,
    const int* __restrict__ weight_idx,
    float* __restrict__ out, int E)
{
    const int gtid = blockIdx.x * blockDim.x + threadIdx.x;
    const int edge = gtid >> 4;
    const int lane = threadIdx.x & 15;
    if (edge >= E) return;

    const int ii = __ldg(&input_idx[edge]);
    const int wi = __ldg(&weight_idx[edge]);
    const float xl = __ldg(&values[(size_t)ii * D + lane]);

    const float4* wr = weight4 + (size_t)wi * (D * D / 4) + lane * 4;
    const float4 a = __ldg(&wr[0]);
    const float4 b = __ldg(&wr[1]);
    const float4 c = __ldg(&wr[2]);
    const float4 d = __ldg(&wr[3]);
    const float wrow[D] = {a.x, a.y, a.z, a.w,
                           b.x, b.y, b.z, b.w,
                           c.x, c.y, c.z, c.w,
                           d.x, d.y, d.z, d.w};

    float acc = 0.0f;
#pragma unroll
    for (int i = 0; i < D; i++)
        acc = fmaf(wrow[i], __shfl_sync(0xFFFFFFFFu, xl, i, 16), acc);

    out[(size_t)edge * D + lane] = acc;
}

extern "C" void kernel_launch(void* const* d_in, const int* in_sizes, int n_in,
                              void* d_out, int out_size)
{
    const float* values     = (const float*)d_in[0];
    const float* weight     = (const float*)d_in[1];
    const int*   input_idx  = (const int*)d_in[2];
    const int*   weight_idx = (const int*)d_in[3];
    float*       out        = (float*)d_out;

    const int E  = in_sizes[2];
    const int NW = in_sizes[1] / (D * D);

    const int chunk = (E + B_SORT - 1) / B_SORT;

    if (NW != NW_MAX || E > PERM_CAP || chunk > 65535) {
        const int threads = 256;
        const long long total = (long long)E * 16;
        edge_linear_fallback<<<(int)((total + threads - 1) / threads), threads>>>(
            values, (const float4*)weight, input_idx, weight_idx, out, E);
        return;
    }

    passA_hist    <<<B_SORT, T_SORT>>>(weight_idx, E, chunk);
    passB1_colscan<<<dim3(NW_MAX / 256, NSEG), 256>>>(B_SORT);
    passB2_scan   <<<1, NW_MAX>>>();
    passC_scatter <<<B_SORT, T_SORT>>>(weight_idx, input_idx, E, chunk);
    compute_sorted_kernel<<<NW_MAX, 256>>>(values, weight, out);
}

// round 12
// speedup vs baseline: 1.4579x; 1.0995x over previous
#include <cuda_runtime.h>
#include <cstdint>

// y[e, o] = sum_i weight[weight_idx[e], o, i] * values[input_idx[e], i]
// E = 1M, D = 16, N_W = 1024.
//
// Pipeline:
//   A) per-block smem histogram of weight_idx, recording each edge's rank
//      within (block, bin) as u16  -> no contended atomics anywhere later
//   B) segmented column scan + bin-total exclusive scan
//   C) atomic-free scatter: p = cur[bin] + rank[e]; writes packed {e, input_idx}
//   D) compute: one CTA per weight, 16 lanes per edge (lane o -> y[o], weight
//      row o in registers). Cooperative 1-wf/edge x gather into conflict-free
//      stride-16 smem, broadcast LDS.128 reads, direct STG.32 y stores
//      (no transpose, no shfl), branchless fast path for full tiles.

#define D 16
#define NW_MAX 1024
#define PERM_CAP (1 << 21)
#define B_SORT 1184
#define T_SORT 256
#define NSEG 8
#define SEG_B ((B_SORT + NSEG - 1) / NSEG)   // 148

__device__ int            g_bhist  [B_SORT * NW_MAX];
__device__ int            g_bstart [B_SORT * NW_MAX];
__device__ int            g_segsum [NSEG * NW_MAX];
__device__ int            g_segbase[NSEG * NW_MAX];
__device__ int            g_tot    [NW_MAX];
__device__ int            g_offsets[NW_MAX];
__device__ unsigned short g_rank[PERM_CAP];
__device__ int2           g_pe  [PERM_CAP];   // {edge id, input_idx}

// ---------------- Pass A: histogram + rank recording ------------------------

__global__ __launch_bounds__(T_SORT) void passA_hist(
    const int* __restrict__ weight_idx, int E, int chunk)
{
    __shared__ int h[NW_MAX];
    const int b = blockIdx.x;
    for (int i = threadIdx.x; i < NW_MAX; i += T_SORT) h[i] = 0;
    __syncthreads();

    const int lo = b * chunk;
    const int hi = min(lo + chunk, E);
    for (int e = lo + threadIdx.x; e < hi; e += T_SORT) {
        const int w = weight_idx[e];
        const int r = atomicAdd(&h[w], 1);       // smem only
        g_rank[e] = (unsigned short)r;           // coalesced 2B store
    }
    __syncthreads();

    for (int i = threadIdx.x; i < NW_MAX; i += T_SORT)
        g_bhist[b * NW_MAX + i] = h[i];
}

// ------------- Pass B1: segmented column scan over blocks (per bin) ---------

__global__ void passB1_colscan(int nblocks)
{
    const int w   = blockIdx.x * blockDim.x + threadIdx.x;
    const int seg = blockIdx.y;
    if (w >= NW_MAX) return;
    const int b0 = seg * SEG_B;
    const int b1 = min(b0 + SEG_B, nblocks);
    int run = 0;
    for (int b = b0; b < b1; b++) {
        const int c = g_bhist[b * NW_MAX + w];   // coalesced across w
        g_bstart[b * NW_MAX + w] = run;
        run += c;
    }
    g_segsum[seg * NW_MAX + w] = run;
}

// ------------- Pass B2: segment combine + exclusive scan of totals ----------

__global__ void passB2_scan()
{
    __shared__ int s[NW_MAX];
    const int w = threadIdx.x;      // 1024 threads
    int base = 0;
#pragma unroll
    for (int g = 0; g < NSEG; g++) {
        g_segbase[g * NW_MAX + w] = base;
        base += g_segsum[g * NW_MAX + w];
    }
    g_tot[w] = base;
    s[w] = base;
    __syncthreads();
#pragma unroll
    for (int off = 1; off < NW_MAX; off <<= 1) {
        const int add = (w >= off) ? s[w - off] : 0;
        __syncthreads();
        s[w] += add;
        __syncthreads();
    }
    g_offsets[w] = s[w] - base;
}

// ---------------- Pass C: atomic-free scatter --------------------------------

__global__ __launch_bounds__(T_SORT) void passC_scatter(
    const int* __restrict__ weight_idx,
    const int* __restrict__ input_idx, int E, int chunk)
{
    __shared__ int cur[NW_MAX];
    const int b   = blockIdx.x;
    const int seg = b / SEG_B;
    for (int i = threadIdx.x; i < NW_MAX; i += T_SORT)
        cur[i] = g_offsets[i] + g_segbase[seg * NW_MAX + i] + g_bstart[b * NW_MAX + i];
    __syncthreads();

    const int lo = b * chunk;
    const int hi = min(lo + chunk, E);
    for (int e = lo + threadIdx.x; e < hi; e += T_SORT) {
        const int w             = weight_idx[e];      // coalesced, independent
        const unsigned short rk = g_rank[e];          // coalesced, independent
        const int ii            = input_idx[e];       // coalesced, independent
        const int p             = cur[w] + (int)rk;   // LDS, no atomics
        g_pe[p] = make_int2(e, ii);                   // single 8B store
    }
}

// ------------- Compute: one CTA per weight, 16 lanes per edge ----------------

__global__ __launch_bounds__(256, 4) void compute_sorted_kernel(
    const float* __restrict__ values,   // [N_POOL, 16]
    const float* __restrict__ weight,   // [N_W, 16, 16] row-major
    float* __restrict__ out)            // [E, 16]
{
    // per-warp staging: 32 slots x 16 floats, stride 16 (64B rows).
    // paired rows (2k, 2k+1) occupy banks 0-15 / 16-31 -> conflict-free.
    __shared__ float sx [8][32 * D];
    __shared__ int2  sei[8][32];

    const int w      = blockIdx.x;
    const int tid    = threadIdx.x;
    const int warpId = tid >> 5;
    const int wl     = tid & 31;
    const int half   = wl >> 4;          // 0 or 1
    const int l16    = wl & 15;          // output index o

    // weight row l16 in registers (both halves hold the same row set)
    float wr[D];
    {
        const float4* wr4 = reinterpret_cast<const float4*>(
            weight + (size_t)w * (D * D) + l16 * D);
        const float4 a = __ldg(&wr4[0]);
        const float4 b = __ldg(&wr4[1]);
        const float4 c = __ldg(&wr4[2]);
        const float4 d = __ldg(&wr4[3]);
        wr[0]=a.x;  wr[1]=a.y;  wr[2]=a.z;  wr[3]=a.w;
        wr[4]=b.x;  wr[5]=b.y;  wr[6]=b.z;  wr[7]=b.w;
        wr[8]=c.x;  wr[9]=c.y;  wr[10]=c.z; wr[11]=c.w;
        wr[12]=d.x; wr[13]=d.y; wr[14]=d.z; wr[15]=d.w;
    }

    const int start = g_offsets[w];
    const int count = g_tot[w];
    float* myx = sx[warpId];
    int2*  mei = sei[warpId];

    for (int base = warpId * 32; base < count; base += 8 * 32) {
        const int nvalid = min(32, count - base);   // warp-uniform

        {
            const int r = base + wl;
            const int2 pe = (r < count) ? g_pe[start + r] : make_int2(0, 0);
            mei[wl] = pe;                            // STS.64, 2 wf
        }
        __syncwarp();

        if (nvalid == 32) {
            // ---- fast path: branchless, fully batched ----
#pragma unroll
            for (int k = 0; k < 16; k++) {
                const int s  = 2 * k + half;
                const int ii = mei[s].y;             // broadcast LDS (2 addrs)
                myx[s * D + l16] =
                    __ldg(&values[(size_t)ii * D + l16]);  // 2 lines / instr
            }
            __syncwarp();

#pragma unroll
            for (int k = 0; k < 16; k++) {
                const int s = 2 * k + half;
                const float4* xr = reinterpret_cast<const float4*>(myx + s * D);
                const float4 x0 = xr[0];             // broadcast LDS.128, 1 wf
                const float4 x1 = xr[1];
                const float4 x2 = xr[2];
                const float4 x3 = xr[3];

                float acc =      wr[0]  * x0.x;
                acc = fmaf(wr[1],  x0.y, acc);
                acc = fmaf(wr[2],  x0.z, acc);
                acc = fmaf(wr[3],  x0.w, acc);
                acc = fmaf(wr[4],  x1.x, acc);
                acc = fmaf(wr[5],  x1.y, acc);
                acc = fmaf(wr[6],  x1.z, acc);
                acc = fmaf(wr[7],  x1.w, acc);
                acc = fmaf(wr[8],  x2.x, acc);
                acc = fmaf(wr[9],  x2.y, acc);
                acc = fmaf(wr[10], x2.z, acc);
                acc = fmaf(wr[11], x2.w, acc);
                acc = fmaf(wr[12], x3.x, acc);
                acc = fmaf(wr[13], x3.y, acc);
                acc = fmaf(wr[14], x3.z, acc);
                acc = fmaf(wr[15], x3.w, acc);

                const int e = mei[s].x;              // broadcast LDS
                out[(size_t)e * D + l16] = acc;      // 2 lines / instr
            }
            __syncwarp();
        } else {
            // ---- tail path (rare): guarded ----
            for (int k = 0; k < 16; k++) {
                const int s = 2 * k + half;
                if (s < nvalid) {
                    const int ii = mei[s].y;
                    myx[s * D + l16] = __ldg(&values[(size_t)ii * D + l16]);
                }
            }
            __syncwarp();

            for (int k = 0; k < 16; k++) {
                const int s = 2 * k + half;
                if (s < nvalid) {
                    const float4* xr =
                        reinterpret_cast<const float4*>(myx + s * D);
                    const float4 x0 = xr[0];
                    const float4 x1 = xr[1];
                    const float4 x2 = xr[2];
                    const float4 x3 = xr[3];

                    float acc =      wr[0]  * x0.x;
                    acc = fmaf(wr[1],  x0.y, acc);
                    acc = fmaf(wr[2],  x0.z, acc);
                    acc = fmaf(wr[3],  x0.w, acc);
                    acc = fmaf(wr[4],  x1.x, acc);
                    acc = fmaf(wr[5],  x1.y, acc);
                    acc = fmaf(wr[6],  x1.z, acc);
                    acc = fmaf(wr[7],  x1.w, acc);
                    acc = fmaf(wr[8],  x2.x, acc);
                    acc = fmaf(wr[9],  x2.y, acc);
                    acc = fmaf(wr[10], x2.z, acc);
                    acc = fmaf(wr[11], x2.w, acc);
                    acc = fmaf(wr[12], x3.x, acc);
                    acc = fmaf(wr[13], x3.y, acc);
                    acc = fmaf(wr[14], x3.z, acc);
                    acc = fmaf(wr[15], x3.w, acc);

                    const int e = mei[s].x;
                    out[(size_t)e * D + l16] = acc;
                }
            }
            __syncwarp();
        }
    }
}

// ---------------- fallback (R1 kernel) for unexpected shapes ----------------

__global__ __launch_bounds__(256) void edge_linear_fallback(
    const float* __restrict__ values,
    const float4* __restrict__ weight4,
    const int* __restrict__ input_idx,
    const int* __restrict__ weight_idx,
    float* __restrict__ out, int E)
{
    const int gtid = blockIdx.x * blockDim.x + threadIdx.x;
    const int edge = gtid >> 4;
    const int lane = threadIdx.x & 15;
    if (edge >= E) return;

    const int ii = __ldg(&input_idx[edge]);
    const int wi = __ldg(&weight_idx[edge]);
    const float xl = __ldg(&values[(size_t)ii * D + lane]);

    const float4* wr = weight4 + (size_t)wi * (D * D / 4) + lane * 4;
    const float4 a = __ldg(&wr[0]);
    const float4 b = __ldg(&wr[1]);
    const float4 c = __ldg(&wr[2]);
    const float4 d = __ldg(&wr[3]);
    const float wrow[D] = {a.x, a.y, a.z, a.w,
                           b.x, b.y, b.z, b.w,
                           c.x, c.y, c.z, c.w,
                           d.x, d.y, d.z, d.w};

    float acc = 0.0f;
#pragma unroll
    for (int i = 0; i < D; i++)
        acc = fmaf(wrow[i], __shfl_sync(0xFFFFFFFFu, xl, i, 16), acc);

    out[(size_t)edge * D + lane] = acc;
}

extern "C" void kernel_launch(void* const* d_in, const int* in_sizes, int n_in,
                              void* d_out, int out_size)
{
    const float* values     = (const float*)d_in[0];
    const float* weight     = (const float*)d_in[1];
    const int*   input_idx  = (const int*)d_in[2];
    const int*   weight_idx = (const int*)d_in[3];
    float*       out        = (float*)d_out;

    const int E  = in_sizes[2];
    const int NW = in_sizes[1] / (D * D);

    const int chunk = (E + B_SORT - 1) / B_SORT;

    if (NW != NW_MAX || E > PERM_CAP || chunk > 65535) {
        const int threads = 256;
        const long long total = (long long)E * 16;
        edge_linear_fallback<<<(int)((total + threads - 1) / threads), threads>>>(
            values, (const float4*)weight, input_idx, weight_idx, out, E);
        return;
    }

    passA_hist    <<<B_SORT, T_SORT>>>(weight_idx, E, chunk);
    passB1_colscan<<<dim3(NW_MAX / 256, NSEG), 256>>>(B_SORT);
    passB2_scan   <<<1, NW_MAX>>>();
    passC_scatter <<<B_SORT, T_SORT>>>(weight_idx, input_idx, E, chunk);
    compute_sorted_kernel<<<NW_MAX, 256>>>(values, weight, out);
}

// round 13
// speedup vs baseline: 1.9743x; 1.3543x over previous
#include <cuda_runtime.h>
#include <cstdint>

// y[e, o] = sum_i weight[weight_idx[e], o, i] * values[input_idx[e], i]
// E = 1M, D = 16, N_W = 1024.
//
// Pipeline (4 kernels):
//   A) per-block smem histogram of weight_idx + per-edge rank (u16)
//   B) segmented column scan over block histograms
//   C) in-block bin scan (replaces old B2) + atomic-free scatter of {e, ii}
//   D) compute: one CTA per weight, 16 lanes per edge, weight rows in regs,
//      SOFTWARE-PIPELINED 2 tiles deep: pe prefetched 2 tiles ahead, x-gather
//      1 tile ahead into registers, STS deferred past compute -> all global
//      latency hidden. Slot broadcast via shfl (register pe), no smem mei.

#define D 16
#define NW_MAX 1024
#define PERM_CAP (1 << 21)
#define B_SORT 1184
#define T_SORT 256
#define NSEG 8
#define SEG_B ((B_SORT + NSEG - 1) / NSEG)   // 148

__device__ int            g_bhist  [B_SORT * NW_MAX];
__device__ int            g_bstart [B_SORT * NW_MAX];
__device__ int            g_segsum [NSEG * NW_MAX];
__device__ int            g_tot    [NW_MAX];
__device__ int            g_offsets[NW_MAX];
__device__ unsigned short g_rank[PERM_CAP];
__device__ int2           g_pe  [PERM_CAP];   // {edge id, input_idx}

// ---------------- Pass A: histogram + rank recording ------------------------

__global__ __launch_bounds__(T_SORT) void passA_hist(
    const int* __restrict__ weight_idx, int E, int chunk)
{
    __shared__ int h[NW_MAX];
    const int b = blockIdx.x;
    for (int i = threadIdx.x; i < NW_MAX; i += T_SORT) h[i] = 0;
    __syncthreads();

    const int lo = b * chunk;
    const int hi = min(lo + chunk, E);
    for (int e = lo + threadIdx.x; e < hi; e += T_SORT) {
        const int w = weight_idx[e];
        const int r = atomicAdd(&h[w], 1);       // smem only
        g_rank[e] = (unsigned short)r;           // coalesced 2B store
    }
    __syncthreads();

    for (int i = threadIdx.x; i < NW_MAX; i += T_SORT)
        g_bhist[b * NW_MAX + i] = h[i];
}

// ------------- Pass B: segmented column scan over blocks (per bin) ----------

__global__ void passB_colscan(int nblocks)
{
    const int w   = blockIdx.x * blockDim.x + threadIdx.x;
    const int seg = blockIdx.y;
    if (w >= NW_MAX) return;
    const int b0 = seg * SEG_B;
    const int b1 = min(b0 + SEG_B, nblocks);
    int run = 0;
    for (int b = b0; b < b1; b++) {
        const int c = g_bhist[b * NW_MAX + w];   // coalesced across w
        g_bstart[b * NW_MAX + w] = run;
        run += c;
    }
    g_segsum[seg * NW_MAX + w] = run;
}

// ------- Pass C: in-block bin scan + atomic-free scatter (replaces B2) ------

__global__ __launch_bounds__(T_SORT) void passC_scan_scatter(
    const int* __restrict__ weight_idx,
    const int* __restrict__ input_idx, int E, int chunk)
{
    __shared__ int cur  [NW_MAX];
    __shared__ int spart[T_SORT];

    const int b   = blockIdx.x;
    const int seg = b / SEG_B;
    const int tid = threadIdx.x;
    const int w0  = tid * 4;                 // this thread's 4 bins

    // per-bin totals + own-segment base (redundant per block, deterministic)
    int tot[4], segb[4];
#pragma unroll
    for (int q = 0; q < 4; q++) { tot[q] = 0; segb[q] = 0; }
#pragma unroll
    for (int g = 0; g < NSEG; g++) {
#pragma unroll
        for (int q = 0; q < 4; q++) {
            const int v = g_segsum[g * NW_MAX + w0 + q];   // coalesced
            if (g < seg) segb[q] += v;
            tot[q] += v;
        }
    }
    const int lsum = tot[0] + tot[1] + tot[2] + tot[3];
    spart[tid] = lsum;
    __syncthreads();

    // Hillis-Steele inclusive scan over 256 thread partials
    int run = lsum;
#pragma unroll
    for (int off = 1; off < T_SORT; off <<= 1) {
        const int add = (tid >= off) ? spart[tid - off] : 0;
        __syncthreads();
        spart[tid] = run = run + add;
        __syncthreads();
    }
    int excl = run - lsum;                    // exclusive over threads

    // offsets per bin + cursor seed
    int off_q[4];
    off_q[0] = excl;
    off_q[1] = off_q[0] + tot[0];
    off_q[2] = off_q[1] + tot[1];
    off_q[3] = off_q[2] + tot[2];
#pragma unroll
    for (int q = 0; q < 4; q++) {
        const int w = w0 + q;
        cur[w] = off_q[q] + segb[q] + g_bstart[b * NW_MAX + w];
        if (b == 0) {                          // publish for compute
            g_offsets[w] = off_q[q];
            g_tot[w]     = tot[q];
        }
    }
    __syncthreads();

    const int lo = b * chunk;
    const int hi = min(lo + chunk, E);
    for (int e = lo + tid; e < hi; e += T_SORT) {
        const int w             = weight_idx[e];      // coalesced, independent
        const unsigned short rk = g_rank[e];          // coalesced, independent
        const int ii            = input_idx[e];       // coalesced, independent
        const int p             = cur[w] + (int)rk;   // LDS, no atomics
        g_pe[p] = make_int2(e, ii);                   // single 8B store
    }
}

// ------------- Compute: pipelined, one CTA per weight, 16 lanes/edge --------

#define MATVEC16(ACC, WR, X0, X1, X2, X3)                     \
    do {                                                      \
        ACC =            WR[0]  * X0.x;                       \
        ACC = fmaf(WR[1],  X0.y, ACC);                        \
        ACC = fmaf(WR[2],  X0.z, ACC);                        \
        ACC = fmaf(WR[3],  X0.w, ACC);                        \
        ACC = fmaf(WR[4],  X1.x, ACC);                        \
        ACC = fmaf(WR[5],  X1.y, ACC);                        \
        ACC = fmaf(WR[6],  X1.z, ACC);                        \
        ACC = fmaf(WR[7],  X1.w, ACC);                        \
        ACC = fmaf(WR[8],  X2.x, ACC);                        \
        ACC = fmaf(WR[9],  X2.y, ACC);                        \
        ACC = fmaf(WR[10], X2.z, ACC);                        \
        ACC = fmaf(WR[11], X2.w, ACC);                        \
        ACC = fmaf(WR[12], X3.x, ACC);                        \
        ACC = fmaf(WR[13], X3.y, ACC);                        \
        ACC = fmaf(WR[14], X3.z, ACC);                        \
        ACC = fmaf(WR[15], X3.w, ACC);                        \
    } while (0)

__global__ __launch_bounds__(256, 4) void compute_sorted_kernel(
    const float* __restrict__ values,   // [N_POOL, 16]
    const float* __restrict__ weight,   // [N_W, 16, 16] row-major
    float* __restrict__ out)            // [E, 16]
{
    __shared__ float sx[8][32 * D];     // 16 KB; paired rows conflict-free

    const int w      = blockIdx.x;
    const int tid    = threadIdx.x;
    const int warpId = tid >> 5;
    const int wl     = tid & 31;
    const int half   = wl >> 4;
    const int l16    = wl & 15;

    float wr[D];
    {
        const float4* wr4 = reinterpret_cast<const float4*>(
            weight + (size_t)w * (D * D) + l16 * D);
        const float4 a = __ldg(&wr4[0]);
        const float4 b = __ldg(&wr4[1]);
        const float4 c = __ldg(&wr4[2]);
        const float4 d = __ldg(&wr4[3]);
        wr[0]=a.x;  wr[1]=a.y;  wr[2]=a.z;  wr[3]=a.w;
        wr[4]=b.x;  wr[5]=b.y;  wr[6]=b.z;  wr[7]=b.w;
        wr[8]=c.x;  wr[9]=c.y;  wr[10]=c.z; wr[11]=c.w;
        wr[12]=d.x; wr[13]=d.y; wr[14]=d.z; wr[15]=d.w;
    }

    const int start = g_offsets[w];
    const int count = g_tot[w];
    float* myx = sx[warpId];

    const int b0 = warpId * 32;
    // full 32-slot tiles at base b0 + j*256
    const int nfull = (count >= b0 + 32) ? ((count - b0 - 32) / 256 + 1) : 0;
    const int pbase = b0 + nfull * 256;          // optional partial tile

    if (nfull > 0) {
        int2 pe_cur, pe_nxt, pe_fut;
        pe_cur = g_pe[start + b0 + wl];

        // prologue: gather tile 0 into regs, prefetch pe(1), stage tile 0
        {
            float gx[16];
#pragma unroll
            for (int k = 0; k < 16; k++) {
                const int s  = 2 * k + half;
                const int ii = __shfl_sync(0xFFFFFFFFu, pe_cur.y, s);
                gx[k] = __ldg(&values[(size_t)ii * D + l16]);
            }
            if (nfull > 1) pe_nxt = g_pe[start + b0 + 256 + wl];
#pragma unroll
            for (int k = 0; k < 16; k++)
                myx[(2 * k + half) * D + l16] = gx[k];
        }
        __syncwarp();

        for (int j = 0; j < nfull; j++) {
            const bool hasN = (j + 1 < nfull);
            if (j + 2 < nfull) pe_fut = g_pe[start + b0 + (j + 2) * 256 + wl];

            // issue next tile's gathers (consumed only after compute)
            float gx[16];
            if (hasN) {
#pragma unroll
                for (int k = 0; k < 16; k++) {
                    const int s  = 2 * k + half;
                    const int ii = __shfl_sync(0xFFFFFFFFu, pe_nxt.y, s);
                    gx[k] = __ldg(&values[(size_t)ii * D + l16]);
                }
            }

            // compute current tile from smem (long; hides the loads above)
#pragma unroll
            for (int k = 0; k < 16; k++) {
                const int s = 2 * k + half;
                const float4* xr = reinterpret_cast<const float4*>(myx + s * D);
                const float4 x0 = xr[0];
                const float4 x1 = xr[1];
                const float4 x2 = xr[2];
                const float4 x3 = xr[3];
                float acc;
                MATVEC16(acc, wr, x0, x1, x2, x3);
                const int e = __shfl_sync(0xFFFFFFFFu, pe_cur.x, s);
                out[(size_t)e * D + l16] = acc;
            }
            __syncwarp();

            if (hasN) {
#pragma unroll
                for (int k = 0; k < 16; k++)
                    myx[(2 * k + half) * D + l16] = gx[k];
            }
            __syncwarp();

            pe_cur = pe_nxt;
            pe_nxt = pe_fut;
        }
    }

    // partial tail tile (at most one per warp); shfls unconditional,
    // only memory ops predicated -> no divergent shfl.
    if (pbase < count) {
        const int nvalid = count - pbase;        // 1..31
        const int r = pbase + wl;
        const int2 pe = (r < count) ? g_pe[start + r] : make_int2(0, 0);

#pragma unroll
        for (int k = 0; k < 16; k++) {
            const int s  = 2 * k + half;
            const int ss = (s < nvalid) ? s : 0;
            const int ii = __shfl_sync(0xFFFFFFFFu, pe.y, ss);
            myx[s * D + l16] = __ldg(&values[(size_t)ii * D + l16]);
        }
        __syncwarp();

#pragma unroll
        for (int k = 0; k < 16; k++) {
            const int s  = 2 * k + half;
            const int ss = (s < nvalid) ? s : 0;
            const int e  = __shfl_sync(0xFFFFFFFFu, pe.x, ss);
            const float4* xr = reinterpret_cast<const float4*>(myx + s * D);
            const float4 x0 = xr[0];
            const float4 x1 = xr[1];
            const float4 x2 = xr[2];
            const float4 x3 = xr[3];
            float acc;
            MATVEC16(acc, wr, x0, x1, x2, x3);
            if (s < nvalid) out[(size_t)e * D + l16] = acc;
        }
        __syncwarp();
    }
}

// ---------------- fallback (R1 kernel) for unexpected shapes ----------------

__global__ __launch_bounds__(256) void edge_linear_fallback(
    const float* __restrict__ values,
    const float4* __restrict__ weight4,
    const int* __restrict__ input_idx,
    const int* __restrict__ weight_idx,
    float* __restrict__ out, int E)
{
    const int gtid = blockIdx.x * blockDim.x + threadIdx.x;
    const int edge = gtid >> 4;
    const int lane = threadIdx.x & 15;
    if (edge >= E) return;

    const int ii = __ldg(&input_idx[edge]);
    const int wi = __ldg(&weight_idx[edge]);
    const float xl = __ldg(&values[(size_t)ii * D + lane]);

    const float4* wrp = weight4 + (size_t)wi * (D * D / 4) + lane * 4;
    const float4 a = __ldg(&wrp[0]);
    const float4 b = __ldg(&wrp[1]);
    const float4 c = __ldg(&wrp[2]);
    const float4 d = __ldg(&wrp[3]);
    const float wrow[D] = {a.x, a.y, a.z, a.w,
                           b.x, b.y, b.z, b.w,
                           c.x, c.y, c.z, c.w,
                           d.x, d.y, d.z, d.w};

    float acc = 0.0f;
#pragma unroll
    for (int i = 0; i < D; i++)
        acc = fmaf(wrow[i], __shfl_sync(0xFFFFFFFFu, xl, i, 16), acc);

    out[(size_t)edge * D + lane] = acc;
}

extern "C" void kernel_launch(void* const* d_in, const int* in_sizes, int n_in,
                              void* d_out, int out_size)
{
    const float* values     = (const float*)d_in[0];
    const float* weight     = (const float*)d_in[1];
    const int*   input_idx  = (const int*)d_in[2];
    const int*   weight_idx = (const int*)d_in[3];
    float*       out        = (float*)d_out;

    const int E  = in_sizes[2];
    const int NW = in_sizes[1] / (D * D);

    const int chunk = (E + B_SORT - 1) / B_SORT;

    if (NW != NW_MAX || E > PERM_CAP || chunk > 65535) {
        const int threads = 256;
        const long long total = (long long)E * 16;
        edge_linear_fallback<<<(int)((total + threads - 1) / threads), threads>>>(
            values, (const float4*)weight, input_idx, weight_idx, out, E);
        return;
    }

    passA_hist       <<<B_SORT, T_SORT>>>(weight_idx, E, chunk);
    passB_colscan    <<<dim3(NW_MAX / 256, NSEG), 256>>>(B_SORT);
    passC_scan_scatter<<<B_SORT, T_SORT>>>(weight_idx, input_idx, E, chunk);
    compute_sorted_kernel<<<NW_MAX, 256>>>(values, weight, out);
}